// round 4
// baseline (speedup 1.0000x reference)
#include <cuda_runtime.h>
#include <cstdint>

#define NN 50000
#define NE 400000
#define DD 128
#define MM 4

// ---------------- device scratch (module globals; no runtime allocation) ----
__device__ __align__(16) float g_Xt[DD * NN];        // 0: X^T (k-major)
__device__ __align__(16) float g_H[NN * DD];         // 1: H = gelu(X W1^T + b1)
__device__ __align__(16) float g_Ht[DD * NN];        // 2: H^T
__device__ __align__(16) float g_G[NN * DD];         // 3: G = gelu(H WA^T)
__device__ __align__(16) float g_featT[2 * DD * NN]; // 4: gelu(concat(agg,H))^T
__device__ __align__(16) float g_aggnode[NN * DD];   // 5: aggregated node features
__device__ __align__(16) float g_W1t[DD * DD];       // 6
__device__ __align__(16) float g_WAt[DD * DD];       // 7
__device__ __align__(16) float g_W2t[2 * DD * DD];   // 8
__device__ __align__(16) float g_T[NN * MM];         // per-node hyper weights
__device__ int g_deg[NN];
__device__ int g_off[NN + 1];
__device__ int g_cur[NN];
__device__ int g_srcs[NE];
__device__ int g_is32;   // 1 if edge_index is int32, 0 if int64

__device__ __forceinline__ float* get_buf(int id) {
    switch (id) {
        case 0: return g_Xt;
        case 1: return g_H;
        case 2: return g_Ht;
        case 3: return g_G;
        case 4: return g_featT;
        case 5: return g_aggnode;
        case 6: return g_W1t;
        case 7: return g_WAt;
        case 8: return g_W2t;
    }
    return g_H;
}

// ---------------- helpers ----------------
__device__ __forceinline__ float gelu_f(float x) {
    return 0.5f * x * (1.0f + erff(x * 0.7071067811865476f));
}

// edge accessor robust to int32 vs int64 storage. which: 0 = src row, 1 = dst row.
__device__ __forceinline__ int edge_at(const void* EI, int which, int e) {
    if (g_is32) return ((const int*)EI)[which * NE + e];
    return (int)((const long long*)EI)[which * NE + e];
}

// ---------------- init: zero histogram + detect edge dtype ----------------
__global__ void k_zerodeg() {
    int i = blockIdx.x * blockDim.x + threadIdx.x;
    if (i < NN) g_deg[i] = 0;
    if (i == 0) g_is32 = 0;
}

// OR of odd 32-bit words among the first NE word-pairs (always in-bounds:
// int32 buffer = 2*NE words, int64 buffer = 4*NE words).
// int64 values < 50000 => all high words zero => flag stays 0.
__global__ void k_detect(const unsigned int* __restrict__ w) {
    unsigned v = 0;
    for (int j = blockIdx.x * blockDim.x + threadIdx.x; j < NE;
         j += gridDim.x * blockDim.x)
        v |= w[2 * j + 1];
    if (v) g_is32 = 1;
}

// ---------------- transpose (optionally fused gelu) ----------------
// src [R][C] row-major -> dst [C][R]. src = srcExt if non-null else get_buf(srcId).
template <bool GELU>
__global__ void k_transpose(const float* __restrict__ srcExt, int srcId,
                            int dstId, long dstOff, int R, int C) {
    const float* src = srcExt ? srcExt : get_buf(srcId);
    float* dst = get_buf(dstId) + dstOff;
    __shared__ float tile[32][33];
    int bx = blockIdx.x * 32, by = blockIdx.y * 32;
    int tx = threadIdx.x, ty = threadIdx.y;
#pragma unroll
    for (int i = 0; i < 32; i += 8) {
        int r = by + ty + i, c = bx + tx;
        if (r < R && c < C) tile[ty + i][tx] = src[(long)r * C + c];
    }
    __syncthreads();
#pragma unroll
    for (int i = 0; i < 32; i += 8) {
        int c = bx + ty + i, r = by + tx;
        if (r < R && c < C) {
            float v = tile[tx][ty + i];
            if (GELU) v = gelu_f(v);
            dst[(long)c * R + r] = v;
        }
    }
}

// ---------------- scalar-FFMA SIMT GEMM (static smem, K-tile 32) ----------
// C[m][n] = act( sum_k At[k][m] * Bt[k][n] + bias[n] )
// At k-major (ld = rows), Bt k-major (ld = 128), C row-major [rows][128].
// CTA 128x128, 256 threads, thread tile 8(M)x8(N).
template <int K, bool GOUT, bool BIAS>
__global__ void __launch_bounds__(256)
k_gemm(int aId, int bId, const float* __restrict__ biasExt,
       float* __restrict__ Cext, int cId, int rows) {
    __shared__ __align__(16) float As[32 * 128];
    __shared__ __align__(16) float Bs[32 * 128];
    const float* At = get_buf(aId);
    const float* Bt = get_buf(bId);
    float* C = Cext ? Cext : get_buf(cId);

    int tid = threadIdx.x;
    int tx = tid & 15;   // N group of 8
    int ty = tid >> 4;   // M group of 8
    int m0 = blockIdx.x * 128;

    float acc[8][8];
#pragma unroll
    for (int i = 0; i < 8; i++)
#pragma unroll
        for (int j = 0; j < 8; j++) acc[i][j] = 0.f;

    for (int kc = 0; kc < K; kc += 32) {
        // cooperative loads: 4 float4 per thread per buffer
#pragma unroll
        for (int w = 0; w < 4; ++w) {
            int f4 = w * 256 + tid;      // 0..1023
            int kk = f4 >> 5;            // 0..31
            int mc = (f4 & 31) << 2;     // 0..124
            float4 va;
            if (m0 + mc < rows)
                va = *(const float4*)(At + (long)(kc + kk) * rows + m0 + mc);
            else
                va = make_float4(0.f, 0.f, 0.f, 0.f);
            *(float4*)(As + kk * 128 + mc) = va;
            *(float4*)(Bs + kk * 128 + mc) = *(const float4*)(Bt + (kc + kk) * 128 + mc);
        }
        __syncthreads();

#pragma unroll
        for (int kk = 0; kk < 32; ++kk) {
            const float* ap = As + kk * 128 + ty * 8;
            float4 aA = *(const float4*)ap;
            float4 aB = *(const float4*)(ap + 4);
            const float* bp = Bs + kk * 128 + tx * 8;
            float4 bA = *(const float4*)bp;
            float4 bB = *(const float4*)(bp + 4);
            float av[8] = {aA.x, aA.y, aA.z, aA.w, aB.x, aB.y, aB.z, aB.w};
            float bv[8] = {bA.x, bA.y, bA.z, bA.w, bB.x, bB.y, bB.z, bB.w};
#pragma unroll
            for (int i = 0; i < 8; i++)
#pragma unroll
                for (int j = 0; j < 8; j++) acc[i][j] += av[i] * bv[j];
        }
        __syncthreads();
    }

    // epilogue
    float bv0[8];
    if (BIAS) {
        float4 u = *(const float4*)(biasExt + tx * 8);
        float4 v = *(const float4*)(biasExt + tx * 8 + 4);
        bv0[0] = u.x; bv0[1] = u.y; bv0[2] = u.z; bv0[3] = u.w;
        bv0[4] = v.x; bv0[5] = v.y; bv0[6] = v.z; bv0[7] = v.w;
    }
#pragma unroll
    for (int i = 0; i < 8; i++) {
        int r = m0 + ty * 8 + i;
        if (r < rows) {
            float o[8];
#pragma unroll
            for (int j = 0; j < 8; j++) {
                float v = acc[i][j];
                if (BIAS) v += bv0[j];
                if (GOUT) v = gelu_f(v);
                o[j] = v;
            }
            float* cp = C + (long)r * 128 + tx * 8;
            *(float4*)cp = make_float4(o[0], o[1], o[2], o[3]);
            *(float4*)(cp + 4) = make_float4(o[4], o[5], o[6], o[7]);
        }
    }
}

// ---------------- T = G @ WB^T  (N x 4), warp per node ----------------
__global__ void k_Tmix(const float* __restrict__ WB) {
    __shared__ float wbs[4 * 128];
    int tid = threadIdx.x;
    for (int i = tid; i < 512; i += 256) wbs[i] = WB[i];
    __syncthreads();
    int warp = tid >> 5, lane = tid & 31;
    int n = blockIdx.x * 8 + warp;
    if (n >= NN) return;
    float4 g4 = *(const float4*)(g_G + (long)n * 128 + lane * 4);
    float p[4];
#pragma unroll
    for (int m = 0; m < 4; m++) {
        float4 w4 = *(const float4*)(wbs + m * 128 + lane * 4);
        p[m] = g4.x * w4.x + g4.y * w4.y + g4.z * w4.z + g4.w * w4.w;
    }
#pragma unroll
    for (int off = 16; off; off >>= 1)
#pragma unroll
        for (int m = 0; m < 4; m++) p[m] += __shfl_xor_sync(0xffffffffu, p[m], off);
    if (lane == 0) *(float4*)(g_T + n * 4) = make_float4(p[0], p[1], p[2], p[3]);
}

// ---------------- edge counting sort by dst ----------------
__global__ void k_hist(const void* __restrict__ EI) {
    for (int e = blockIdx.x * blockDim.x + threadIdx.x; e < NE;
         e += gridDim.x * blockDim.x) {
        int d = edge_at(EI, 1, e);
        if (d >= 0 && d < NN) atomicAdd(&g_deg[d], 1);
    }
}

__global__ void k_scan() {
    __shared__ int smv[1024];
    int t = threadIdx.x;
    const int CH = 49; // 1024*49 >= 50000
    int base = t * CH;
    int s = 0;
    for (int i = 0; i < CH; i++) {
        int idx = base + i;
        if (idx < NN) s += g_deg[idx];
    }
    smv[t] = s;
    __syncthreads();
    for (int off = 1; off < 1024; off <<= 1) {
        int v = (t >= off) ? smv[t - off] : 0;
        __syncthreads();
        smv[t] += v;
        __syncthreads();
    }
    int run = smv[t] - s; // exclusive prefix for this thread's chunk
    for (int i = 0; i < CH; i++) {
        int idx = base + i;
        if (idx < NN) {
            g_off[idx] = run;
            g_cur[idx] = run;
            run += g_deg[idx];
        }
    }
    if (t == 0) g_off[NN] = NE;
}

__global__ void k_scatter(const void* __restrict__ EI) {
    for (int e = blockIdx.x * blockDim.x + threadIdx.x; e < NE;
         e += gridDim.x * blockDim.x) {
        int d = edge_at(EI, 1, e);
        int s = edge_at(EI, 0, e);
        if (d >= 0 && d < NN) {
            int p = atomicAdd(&g_cur[d], 1);
            g_srcs[p] = s;
        }
    }
}

// ---------------- per-node aggregation (warp per node) ----------------
// acc[h][m] = sum_{e:dst=n} H[src,h]*T[src,m];  S[m] = sum_{e:dst=n} T[src,m]
// aggnode[n][h] = (sum_m gelu(acc[h][m]) * S[m]) / max(deg,1)
__global__ void k_agg() {
    int warp = threadIdx.x >> 5, lane = threadIdx.x & 31;
    int n = blockIdx.x * 8 + warp;
    if (n >= NN) return;
    int beg = g_off[n], end = g_off[n + 1];
    float a0[4] = {0, 0, 0, 0}, a1[4] = {0, 0, 0, 0};
    float a2[4] = {0, 0, 0, 0}, a3[4] = {0, 0, 0, 0};
    float S[4] = {0, 0, 0, 0};
    for (int i = beg; i < end; ++i) {
        int s = g_srcs[i];
        float4 t4 = *(const float4*)(g_T + s * 4);
        const float* h = g_H + (long)s * 128;
        float h0 = h[lane], h1 = h[lane + 32], h2 = h[lane + 64], h3 = h[lane + 96];
        S[0] += t4.x; S[1] += t4.y; S[2] += t4.z; S[3] += t4.w;
        a0[0] += h0 * t4.x; a0[1] += h0 * t4.y; a0[2] += h0 * t4.z; a0[3] += h0 * t4.w;
        a1[0] += h1 * t4.x; a1[1] += h1 * t4.y; a1[2] += h1 * t4.z; a1[3] += h1 * t4.w;
        a2[0] += h2 * t4.x; a2[1] += h2 * t4.y; a2[2] += h2 * t4.z; a2[3] += h2 * t4.w;
        a3[0] += h3 * t4.x; a3[1] += h3 * t4.y; a3[2] += h3 * t4.z; a3[3] += h3 * t4.w;
    }
    int cnt = end - beg;
    float inv = 1.0f / (float)(cnt > 1 ? cnt : 1);
    float* outp = g_aggnode + (long)n * 128;
    outp[lane] =
        (gelu_f(a0[0]) * S[0] + gelu_f(a0[1]) * S[1] + gelu_f(a0[2]) * S[2] +
         gelu_f(a0[3]) * S[3]) * inv;
    outp[lane + 32] =
        (gelu_f(a1[0]) * S[0] + gelu_f(a1[1]) * S[1] + gelu_f(a1[2]) * S[2] +
         gelu_f(a1[3]) * S[3]) * inv;
    outp[lane + 64] =
        (gelu_f(a2[0]) * S[0] + gelu_f(a2[1]) * S[1] + gelu_f(a2[2]) * S[2] +
         gelu_f(a2[3]) * S[3]) * inv;
    outp[lane + 96] =
        (gelu_f(a3[0]) * S[0] + gelu_f(a3[1]) * S[1] + gelu_f(a3[2]) * S[2] +
         gelu_f(a3[3]) * S[3]) * inv;
}

// ---------------- host launch: kernel launches ONLY ----------------
extern "C" void kernel_launch(void* const* d_in, const int* in_sizes, int n_in,
                              void* d_out, int out_size) {
    const float* X = (const float*)d_in[0];
    const void* EI = d_in[1];
    const float* W1 = (const float*)d_in[2];
    const float* b1 = (const float*)d_in[3];
    const float* WA = (const float*)d_in[4];
    const float* WB = (const float*)d_in[5];
    const float* W2 = (const float*)d_in[6];
    const float* b2 = (const float*)d_in[7];
    float* out = (float*)d_out;

    k_zerodeg<<<(NN + 255) / 256, 256>>>();
    k_detect<<<256, 256>>>((const unsigned int*)EI);

    dim3 tb(32, 8);
    int gy = (NN + 31) / 32; // 1563
    // transposes of inputs/weights into k-major operands
    k_transpose<false><<<dim3(4, gy), tb>>>(X, -1, 0, 0, NN, DD);       // X -> Xt
    k_transpose<false><<<dim3(4, 4), tb>>>(W1, -1, 6, 0, DD, DD);       // W1 -> W1t
    k_transpose<false><<<dim3(4, 4), tb>>>(WA, -1, 7, 0, DD, DD);       // WA -> WAt
    k_transpose<false><<<dim3(8, 4), tb>>>(W2, -1, 8, 0, DD, 2 * DD);   // W2 -> W2t

    int gg = (NN + 127) / 128; // 391
    // H = gelu(X W1^T + b1)
    k_gemm<128, true, true><<<gg, 256>>>(0, 6, b1, nullptr, 1, NN);
    // Ht
    k_transpose<false><<<dim3(4, gy), tb>>>(nullptr, 1, 2, 0, NN, DD);
    // G = gelu(H WA^T)
    k_gemm<128, true, false><<<gg, 256>>>(2, 7, nullptr, nullptr, 3, NN);
    // T = G WB^T
    k_Tmix<<<(NN + 7) / 8, 256>>>(WB);

    // edge counting sort by dst
    k_hist<<<512, 256>>>(EI);
    k_scan<<<1, 1024>>>();
    k_scatter<<<512, 256>>>(EI);

    // fused aggregation: cross scatter + gelu + mix contraction + mean
    k_agg<<<(NN + 7) / 8, 256>>>();

    // featT = gelu(concat(aggnode, H))^T
    k_transpose<true><<<dim3(4, gy), tb>>>(nullptr, 5, 4, 0, NN, DD);
    k_transpose<true><<<dim3(4, gy), tb>>>(nullptr, 1, 4, (long)DD * NN, NN, DD);

    // out = feat W2^T + b2
    k_gemm<256, false, true><<<gg, 256>>>(4, 8, b2, out, -1, NN);
}

// round 5
// speedup vs baseline: 1.1583x; 1.1583x over previous
#include <cuda_runtime.h>
#include <cstdint>

#define NN 50000
#define NE 400000
#define DD 128
#define MM 4

// ---------------- device scratch ----------------
__device__ __align__(16) float g_H[NN * DD];       // 1: H = gelu(X W1^T + b1)
__device__ __align__(16) float g_G[NN * DD];       // 3: G = gelu(H WA^T)
__device__ __align__(16) float g_aggnode[NN * DD]; // 5: gelu(aggregated features)
__device__ __align__(16) float g_T[NN * MM];       // per-node hyper weights
__device__ int g_deg[NN];
__device__ int g_off[NN + 1];
__device__ int g_cur[NN];
__device__ int g_srcs[NE];
__device__ int g_is32; // 1 if edge_index is int32, 0 if int64

__device__ __forceinline__ float* get_buf(int id) {
    switch (id) {
        case 1: return g_H;
        case 3: return g_G;
        case 5: return g_aggnode;
    }
    return g_H;
}

// ---------------- helpers ----------------
__device__ __forceinline__ float gelu_f(float x) {
    return 0.5f * x * (1.0f + erff(x * 0.7071067811865476f));
}

__device__ __forceinline__ unsigned tf32u(float x) {
    unsigned r;
    asm("cvt.rna.tf32.f32 %0, %1;" : "=r"(r) : "f"(x));
    return r;
}

__device__ __forceinline__ void mma_tf32(float* d, const unsigned* a,
                                         unsigned b0, unsigned b1) {
    asm volatile(
        "mma.sync.aligned.m16n8k8.row.col.f32.tf32.tf32.f32 "
        "{%0,%1,%2,%3}, {%4,%5,%6,%7}, {%8,%9}, {%0,%1,%2,%3};\n"
        : "+f"(d[0]), "+f"(d[1]), "+f"(d[2]), "+f"(d[3])
        : "r"(a[0]), "r"(a[1]), "r"(a[2]), "r"(a[3]), "r"(b0), "r"(b1));
}

// edge accessor robust to int32 vs int64 storage. which: 0 = src, 1 = dst.
__device__ __forceinline__ int edge_at(const void* EI, int which, int e) {
    if (g_is32) return ((const int*)EI)[which * NE + e];
    return (int)((const long long*)EI)[which * NE + e];
}

// ---------------- init: zero histogram + detect edge dtype ----------------
__global__ void k_zerodeg() {
    int i = blockIdx.x * blockDim.x + threadIdx.x;
    if (i < NN) g_deg[i] = 0;
    if (i == 0) g_is32 = 0;
}

__global__ void k_detect(const unsigned int* __restrict__ w) {
    unsigned v = 0;
    for (int j = blockIdx.x * blockDim.x + threadIdx.x; j < NE;
         j += gridDim.x * blockDim.x)
        v |= w[2 * j + 1];
    if (v) g_is32 = 1;
}

// ---------------- tf32 tensor-core GEMM, 3-term compensated split ---------
// C[m][n] = act( sum_k A[m][k] * W[n][k] + bias[n] ),  N = 128 fixed.
// A row-major (logical row stride 128; for SPLITA the 256-wide A is
// [aggnode | gelu(H)] both stride 128). W row-major [128][K].
// CTA tile 128x128, 8 warps (4M x 2N), warp tile 32x64, K-chunk 16.
template <int K, bool GOUT, bool BIAS, bool SPLITA>
__global__ void __launch_bounds__(256)
k_gemm_tc(const float* __restrict__ Aext, int aId, int a2Id,
          const float* __restrict__ bias, const float* __restrict__ W,
          float* __restrict__ Cext, int cId, int rows) {
    __shared__ unsigned As[2][128][20]; // [hi/lo][m][k] pad->20 (conflict-free)
    __shared__ unsigned Bs[2][128][20]; // [hi/lo][n][k]

    const float* A1 = Aext ? Aext : get_buf(aId);
    const float* A2 = SPLITA ? get_buf(a2Id) : nullptr;
    float* C = Cext ? Cext : get_buf(cId);

    int tid = threadIdx.x;
    int wid = tid >> 5, lane = tid & 31;
    int wm = (wid >> 1) * 32;  // warp M base within CTA
    int wn = (wid & 1) * 64;   // warp N base within CTA
    int g = lane >> 2, tg = lane & 3;
    int m0 = blockIdx.x * 128;

    float d[2][8][4];
#pragma unroll
    for (int t = 0; t < 2; t++)
#pragma unroll
        for (int nt = 0; nt < 8; nt++)
#pragma unroll
            for (int j = 0; j < 4; j++) d[t][nt][j] = 0.f;

    for (int kc = 0; kc < K; kc += 16) {
        // select A source for this chunk (uniform across CTA)
        const float* Ap = A1;
        int kk = kc;
        bool ag = false;
        if (SPLITA && kc >= 128) {
            Ap = A2;
            kk = kc - 128;
            ag = true;
        }
        // cooperative load + tf32 hi/lo split: 2 float4 per thread per operand
#pragma unroll
        for (int i = 0; i < 2; i++) {
            int f = tid + i * 256;    // 0..511
            int m = f >> 2;           // 0..127
            int kq = (f & 3) << 2;    // 0,4,8,12
            // ---- A ----
            int gm = m0 + m;
            float4 v = make_float4(0.f, 0.f, 0.f, 0.f);
            if (gm < rows) v = *(const float4*)(Ap + (long)gm * 128 + kk + kq);
            if (SPLITA && ag) {
                v.x = gelu_f(v.x); v.y = gelu_f(v.y);
                v.z = gelu_f(v.z); v.w = gelu_f(v.w);
            }
            uint4 hi, lo;
            hi.x = tf32u(v.x); lo.x = tf32u(v.x - __uint_as_float(hi.x));
            hi.y = tf32u(v.y); lo.y = tf32u(v.y - __uint_as_float(hi.y));
            hi.z = tf32u(v.z); lo.z = tf32u(v.z - __uint_as_float(hi.z));
            hi.w = tf32u(v.w); lo.w = tf32u(v.w - __uint_as_float(hi.w));
            *(uint4*)&As[0][m][kq] = hi;
            *(uint4*)&As[1][m][kq] = lo;
            // ---- B (weights, n index = m) ----
            float4 w = *(const float4*)(W + (long)m * K + kc + kq);
            uint4 whi, wlo;
            whi.x = tf32u(w.x); wlo.x = tf32u(w.x - __uint_as_float(whi.x));
            whi.y = tf32u(w.y); wlo.y = tf32u(w.y - __uint_as_float(whi.y));
            whi.z = tf32u(w.z); wlo.z = tf32u(w.z - __uint_as_float(whi.z));
            whi.w = tf32u(w.w); wlo.w = tf32u(w.w - __uint_as_float(whi.w));
            *(uint4*)&Bs[0][m][kq] = whi;
            *(uint4*)&Bs[1][m][kq] = wlo;
        }
        __syncthreads();

#pragma unroll
        for (int ks = 0; ks < 16; ks += 8) {
            unsigned ah[2][4], al[2][4];
#pragma unroll
            for (int t = 0; t < 2; t++) {
                int r0 = wm + t * 16 + g;
                ah[t][0] = As[0][r0][ks + tg];
                ah[t][1] = As[0][r0 + 8][ks + tg];
                ah[t][2] = As[0][r0][ks + tg + 4];
                ah[t][3] = As[0][r0 + 8][ks + tg + 4];
                al[t][0] = As[1][r0][ks + tg];
                al[t][1] = As[1][r0 + 8][ks + tg];
                al[t][2] = As[1][r0][ks + tg + 4];
                al[t][3] = As[1][r0 + 8][ks + tg + 4];
            }
#pragma unroll
            for (int nt = 0; nt < 8; nt++) {
                int n0 = wn + nt * 8 + g;
                unsigned bh0 = Bs[0][n0][ks + tg];
                unsigned bh1 = Bs[0][n0][ks + tg + 4];
                unsigned bl0 = Bs[1][n0][ks + tg];
                unsigned bl1 = Bs[1][n0][ks + tg + 4];
#pragma unroll
                for (int t = 0; t < 2; t++) {
                    mma_tf32(d[t][nt], ah[t], bh0, bh1); // hi*hi
                    mma_tf32(d[t][nt], al[t], bh0, bh1); // lo*hi
                    mma_tf32(d[t][nt], ah[t], bl0, bl1); // hi*lo
                }
            }
        }
        __syncthreads();
    }

    // epilogue: d[t][nt] covers rows {r, r+8}, cols {c, c+1}
#pragma unroll
    for (int t = 0; t < 2; t++) {
        int r = m0 + wm + t * 16 + g;
#pragma unroll
        for (int nt = 0; nt < 8; nt++) {
            int c = wn + nt * 8 + 2 * tg;
            float b0 = 0.f, b1 = 0.f;
            if (BIAS) { b0 = bias[c]; b1 = bias[c + 1]; }
            if (r < rows) {
                float v0 = d[t][nt][0] + b0, v1 = d[t][nt][1] + b1;
                if (GOUT) { v0 = gelu_f(v0); v1 = gelu_f(v1); }
                *(float2*)(C + (long)r * 128 + c) = make_float2(v0, v1);
            }
            if (r + 8 < rows) {
                float v2 = d[t][nt][2] + b0, v3 = d[t][nt][3] + b1;
                if (GOUT) { v2 = gelu_f(v2); v3 = gelu_f(v3); }
                *(float2*)(C + (long)(r + 8) * 128 + c) = make_float2(v2, v3);
            }
        }
    }
}

// ---------------- T = G @ WB^T  (N x 4), warp per node ----------------
__global__ void k_Tmix(const float* __restrict__ WB) {
    __shared__ float wbs[4 * 128];
    int tid = threadIdx.x;
    for (int i = tid; i < 512; i += 256) wbs[i] = WB[i];
    __syncthreads();
    int warp = tid >> 5, lane = tid & 31;
    int n = blockIdx.x * 8 + warp;
    if (n >= NN) return;
    float4 g4 = *(const float4*)(g_G + (long)n * 128 + lane * 4);
    float p[4];
#pragma unroll
    for (int m = 0; m < 4; m++) {
        float4 w4 = *(const float4*)(wbs + m * 128 + lane * 4);
        p[m] = g4.x * w4.x + g4.y * w4.y + g4.z * w4.z + g4.w * w4.w;
    }
#pragma unroll
    for (int off = 16; off; off >>= 1)
#pragma unroll
        for (int m = 0; m < 4; m++) p[m] += __shfl_xor_sync(0xffffffffu, p[m], off);
    if (lane == 0) *(float4*)(g_T + n * 4) = make_float4(p[0], p[1], p[2], p[3]);
}

// ---------------- edge counting sort by dst ----------------
__global__ void k_hist(const void* __restrict__ EI) {
    for (int e = blockIdx.x * blockDim.x + threadIdx.x; e < NE;
         e += gridDim.x * blockDim.x) {
        int d = edge_at(EI, 1, e);
        if (d >= 0 && d < NN) atomicAdd(&g_deg[d], 1);
    }
}

__global__ void k_scan() {
    __shared__ int smv[1024];
    int t = threadIdx.x;
    const int CH = 49; // 1024*49 >= 50000
    int base = t * CH;
    int s = 0;
    for (int i = 0; i < CH; i++) {
        int idx = base + i;
        if (idx < NN) s += g_deg[idx];
    }
    smv[t] = s;
    __syncthreads();
    for (int off = 1; off < 1024; off <<= 1) {
        int v = (t >= off) ? smv[t - off] : 0;
        __syncthreads();
        smv[t] += v;
        __syncthreads();
    }
    int run = smv[t] - s; // exclusive prefix for this thread's chunk
    for (int i = 0; i < CH; i++) {
        int idx = base + i;
        if (idx < NN) {
            g_off[idx] = run;
            g_cur[idx] = run;
            run += g_deg[idx];
        }
    }
    if (t == 0) g_off[NN] = NE;
}

__global__ void k_scatter(const void* __restrict__ EI) {
    for (int e = blockIdx.x * blockDim.x + threadIdx.x; e < NE;
         e += gridDim.x * blockDim.x) {
        int d = edge_at(EI, 1, e);
        int s = edge_at(EI, 0, e);
        if (d >= 0 && d < NN) {
            int p = atomicAdd(&g_cur[d], 1);
            g_srcs[p] = s;
        }
    }
}

// ---------------- per-node aggregation (warp per node) ----------------
// acc[h][m] = sum_{e:dst=n} H[src,h]*T[src,m];  S[m] = sum_{e:dst=n} T[src,m]
// aggnode[n][h] = gelu( (sum_m gelu(acc[h][m]) * S[m]) / max(deg,1) )
// (outer gelu = the feat-concat gelu, fused here)
__global__ void k_agg() {
    int warp = threadIdx.x >> 5, lane = threadIdx.x & 31;
    int n = blockIdx.x * 8 + warp;
    if (n >= NN) return;
    int beg = g_off[n], end = g_off[n + 1];
    float a0[4] = {0, 0, 0, 0}, a1[4] = {0, 0, 0, 0};
    float a2[4] = {0, 0, 0, 0}, a3[4] = {0, 0, 0, 0};
    float S[4] = {0, 0, 0, 0};
    for (int i = beg; i < end; ++i) {
        int s = g_srcs[i];
        float4 t4 = *(const float4*)(g_T + s * 4);
        const float* h = g_H + (long)s * 128;
        float h0 = h[lane], h1 = h[lane + 32], h2 = h[lane + 64], h3 = h[lane + 96];
        S[0] += t4.x; S[1] += t4.y; S[2] += t4.z; S[3] += t4.w;
        a0[0] += h0 * t4.x; a0[1] += h0 * t4.y; a0[2] += h0 * t4.z; a0[3] += h0 * t4.w;
        a1[0] += h1 * t4.x; a1[1] += h1 * t4.y; a1[2] += h1 * t4.z; a1[3] += h1 * t4.w;
        a2[0] += h2 * t4.x; a2[1] += h2 * t4.y; a2[2] += h2 * t4.z; a2[3] += h2 * t4.w;
        a3[0] += h3 * t4.x; a3[1] += h3 * t4.y; a3[2] += h3 * t4.z; a3[3] += h3 * t4.w;
    }
    int cnt = end - beg;
    float inv = 1.0f / (float)(cnt > 1 ? cnt : 1);
    float* outp = g_aggnode + (long)n * 128;
    outp[lane] = gelu_f(
        (gelu_f(a0[0]) * S[0] + gelu_f(a0[1]) * S[1] + gelu_f(a0[2]) * S[2] +
         gelu_f(a0[3]) * S[3]) * inv);
    outp[lane + 32] = gelu_f(
        (gelu_f(a1[0]) * S[0] + gelu_f(a1[1]) * S[1] + gelu_f(a1[2]) * S[2] +
         gelu_f(a1[3]) * S[3]) * inv);
    outp[lane + 64] = gelu_f(
        (gelu_f(a2[0]) * S[0] + gelu_f(a2[1]) * S[1] + gelu_f(a2[2]) * S[2] +
         gelu_f(a2[3]) * S[3]) * inv);
    outp[lane + 96] = gelu_f(
        (gelu_f(a3[0]) * S[0] + gelu_f(a3[1]) * S[1] + gelu_f(a3[2]) * S[2] +
         gelu_f(a3[3]) * S[3]) * inv);
}

// ---------------- host launch: kernel launches ONLY ----------------
extern "C" void kernel_launch(void* const* d_in, const int* in_sizes, int n_in,
                              void* d_out, int out_size) {
    const float* X = (const float*)d_in[0];
    const void* EI = d_in[1];
    const float* W1 = (const float*)d_in[2];
    const float* b1 = (const float*)d_in[3];
    const float* WA = (const float*)d_in[4];
    const float* WB = (const float*)d_in[5];
    const float* W2 = (const float*)d_in[6];
    const float* b2 = (const float*)d_in[7];
    float* out = (float*)d_out;

    k_zerodeg<<<(NN + 255) / 256, 256>>>();
    k_detect<<<256, 256>>>((const unsigned int*)EI);

    int gg = (NN + 127) / 128; // 391
    // H = gelu(X W1^T + b1)
    k_gemm_tc<128, true, true, false><<<gg, 256>>>(X, -1, -1, b1, W1, nullptr, 1, NN);
    // G = gelu(H WA^T)
    k_gemm_tc<128, true, false, false><<<gg, 256>>>(nullptr, 1, -1, nullptr, WA,
                                                    nullptr, 3, NN);
    // T = G WB^T
    k_Tmix<<<(NN + 7) / 8, 256>>>(WB);

    // edge counting sort by dst
    k_hist<<<512, 256>>>(EI);
    k_scan<<<1, 1024>>>();
    k_scatter<<<512, 256>>>(EI);

    // fused aggregation (+ final concat-gelu on the agg half)
    k_agg<<<(NN + 7) / 8, 256>>>();

    // out = [gelu(agg) | gelu(H)] W2^T + b2   (virtual concat, gelu(H) fused in load)
    k_gemm_tc<256, false, true, true><<<gg, 256>>>(nullptr, 5, 1, b2, W2, out, -1, NN);
}

// round 6
// speedup vs baseline: 1.3859x; 1.1965x over previous
#include <cuda_runtime.h>
#include <cuda_bf16.h>
#include <cstdint>

#define NN 50000
#define NE 400000
#define DD 128
#define MM 4

// ---------------- device scratch ----------------
__device__ __align__(16) float g_H[NN * DD];       // 1: H = gelu(X W1^T + b1)
__device__ __align__(16) float g_aggnode[NN * DD]; // 5: gelu(aggregated features)
__device__ __align__(16) float g_T[NN * MM];       // per-node hyper weights
__device__ int g_deg[NN];
__device__ int g_off[NN + 1];
__device__ int g_cur[NN];
__device__ int g_srcs[NE];
__device__ int g_is32; // 1 if edge_index is int32, 0 if int64

__device__ __forceinline__ float* get_buf(int id) {
    switch (id) {
        case 1: return g_H;
        case 5: return g_aggnode;
    }
    return g_H;
}

// ---------------- helpers ----------------
__device__ __forceinline__ float gelu_f(float x) {
    return 0.5f * x * (1.0f + erff(x * 0.7071067811865476f));
}

// pack two floats into bf16x2 (x -> low, y -> high)
__device__ __forceinline__ unsigned pack2bf(float x, float y) {
    __nv_bfloat162 p = __floats2bfloat162_rn(x, y);
    return *reinterpret_cast<unsigned*>(&p);
}

// split (x,y) into hi bf16 pair + residual-lo bf16 pair
__device__ __forceinline__ void split2(float x, float y, unsigned& hi, unsigned& lo) {
    __nv_bfloat16 hx = __float2bfloat16(x);
    __nv_bfloat16 hy = __float2bfloat16(y);
    __nv_bfloat162 ph;
    ph.x = hx;
    ph.y = hy;
    hi = *reinterpret_cast<unsigned*>(&ph);
    lo = pack2bf(x - __bfloat162float(hx), y - __bfloat162float(hy));
}

__device__ __forceinline__ void mma_bf16(float* d, const unsigned* a,
                                         unsigned b0, unsigned b1) {
    asm volatile(
        "mma.sync.aligned.m16n8k16.row.col.f32.bf16.bf16.f32 "
        "{%0,%1,%2,%3}, {%4,%5,%6,%7}, {%8,%9}, {%0,%1,%2,%3};\n"
        : "+f"(d[0]), "+f"(d[1]), "+f"(d[2]), "+f"(d[3])
        : "r"(a[0]), "r"(a[1]), "r"(a[2]), "r"(a[3]), "r"(b0), "r"(b1));
}

// edge accessor robust to int32 vs int64 storage. which: 0 = src, 1 = dst.
__device__ __forceinline__ int edge_at(const void* EI, int which, int e) {
    if (g_is32) return ((const int*)EI)[which * NE + e];
    return (int)((const long long*)EI)[which * NE + e];
}

// ---------------- init ----------------
__global__ void k_zerodeg() {
    int i = blockIdx.x * blockDim.x + threadIdx.x;
    if (i < NN) g_deg[i] = 0;
    if (i == 0) g_is32 = 0;
}

__global__ void k_detect(const unsigned int* __restrict__ w) {
    unsigned v = 0;
    for (int j = blockIdx.x * blockDim.x + threadIdx.x; j < NE;
         j += gridDim.x * blockDim.x)
        v |= w[2 * j + 1];
    if (v) g_is32 = 1;
}

// ---------------- bf16-split tensor-core GEMM (3-term compensated) --------
// C[m][n] = act( sum_k A[m][k] * W[n][k] + bias[n] ),  N = 128.
// A row-major stride 128 (SPLITA: k<128 from A1, k>=128 from gelu(A2)).
// W row-major [128][K]. CTA 128x128, 8 warps (4M x 2N), warp 32x64, k-chunk 16.
// TMIX: skip C write; instead T[m][j] = sum_n gelu(C[m][n]) * WB[j][n].
template <int K, bool GOUT, bool BIAS, bool SPLITA, bool TMIX>
__global__ void __launch_bounds__(256)
k_gemm_bf(const float* __restrict__ Aext, int aId, int a2Id,
          const float* __restrict__ bias, const float* __restrict__ W,
          const float* __restrict__ WB, float* __restrict__ Cext, int cId,
          int rows) {
    __shared__ __align__(16) unsigned As[2][128][12]; // [hi/lo][m][k-pair] pad 12
    __shared__ __align__(16) unsigned Bs[2][128][12]; // [hi/lo][n][k-pair]
    __shared__ float Tred[128][4];
    __shared__ float wbs[4 * 128];

    const float* A1 = Aext ? Aext : get_buf(aId);
    const float* A2 = SPLITA ? get_buf(a2Id) : nullptr;
    float* C = Cext ? Cext : get_buf(cId);

    int tid = threadIdx.x;
    int wid = tid >> 5, lane = tid & 31;
    int wm = (wid >> 1) * 32;  // warp M base
    int wn = (wid & 1) * 64;   // warp N base
    int g = lane >> 2, tg = lane & 3;
    int m0 = blockIdx.x * 128;

    if (TMIX) {
        for (int i = tid; i < 512; i += 256) wbs[i] = WB[i];
        if (tid < 128) {
            Tred[tid][0] = 0.f; Tred[tid][1] = 0.f;
            Tred[tid][2] = 0.f; Tred[tid][3] = 0.f;
        }
    }

    float d[2][8][4];
#pragma unroll
    for (int t = 0; t < 2; t++)
#pragma unroll
        for (int nt = 0; nt < 8; nt++)
#pragma unroll
            for (int j = 0; j < 4; j++) d[t][nt][j] = 0.f;

    for (int kc = 0; kc < K; kc += 16) {
        const float* Ap = A1;
        int kk = kc;
        bool ag = false;
        if (SPLITA && kc >= 128) {
            Ap = A2;
            kk = kc - 128;
            ag = true;
        }
        // cooperative load + bf16 hi/lo split: 2 float4 per thread per operand
#pragma unroll
        for (int i = 0; i < 2; i++) {
            int f = tid + i * 256;    // 0..511
            int m = f >> 2;           // 0..127
            int kq = (f & 3) << 2;    // 0,4,8,12
            // ---- A ----
            int gm = m0 + m;
            float4 v = make_float4(0.f, 0.f, 0.f, 0.f);
            if (gm < rows) v = *(const float4*)(Ap + (long)gm * 128 + kk + kq);
            if (SPLITA && ag) {
                v.x = gelu_f(v.x); v.y = gelu_f(v.y);
                v.z = gelu_f(v.z); v.w = gelu_f(v.w);
            }
            unsigned h0, l0, h1, l1;
            split2(v.x, v.y, h0, l0);
            split2(v.z, v.w, h1, l1);
            *(uint2*)&As[0][m][kq >> 1] = make_uint2(h0, h1);
            *(uint2*)&As[1][m][kq >> 1] = make_uint2(l0, l1);
            // ---- B (weights; n index = m) ----
            float4 w = *(const float4*)(W + (long)m * K + kc + kq);
            unsigned wh0, wl0, wh1, wl1;
            split2(w.x, w.y, wh0, wl0);
            split2(w.z, w.w, wh1, wl1);
            *(uint2*)&Bs[0][m][kq >> 1] = make_uint2(wh0, wh1);
            *(uint2*)&Bs[1][m][kq >> 1] = make_uint2(wl0, wl1);
        }
        __syncthreads();

        unsigned ah[2][4], al[2][4];
#pragma unroll
        for (int t = 0; t < 2; t++) {
            int r0 = wm + t * 16 + g;
            ah[t][0] = As[0][r0][tg];
            ah[t][1] = As[0][r0 + 8][tg];
            ah[t][2] = As[0][r0][tg + 4];
            ah[t][3] = As[0][r0 + 8][tg + 4];
            al[t][0] = As[1][r0][tg];
            al[t][1] = As[1][r0 + 8][tg];
            al[t][2] = As[1][r0][tg + 4];
            al[t][3] = As[1][r0 + 8][tg + 4];
        }
#pragma unroll
        for (int nt = 0; nt < 8; nt++) {
            int n0 = wn + nt * 8 + g;
            unsigned bh0 = Bs[0][n0][tg];
            unsigned bh1 = Bs[0][n0][tg + 4];
            unsigned bl0 = Bs[1][n0][tg];
            unsigned bl1 = Bs[1][n0][tg + 4];
#pragma unroll
            for (int t = 0; t < 2; t++) {
                mma_bf16(d[t][nt], ah[t], bh0, bh1); // hi*hi
                mma_bf16(d[t][nt], al[t], bh0, bh1); // lo*hi
                mma_bf16(d[t][nt], ah[t], bl0, bl1); // hi*lo
            }
        }
        __syncthreads();
    }

    // ---------------- epilogue ----------------
    float tp[4][4]; // TMIX partials: [local row slot][mix]
    if (TMIX) {
#pragma unroll
        for (int s = 0; s < 4; s++)
#pragma unroll
            for (int m = 0; m < 4; m++) tp[s][m] = 0.f;
    }
#pragma unroll
    for (int t = 0; t < 2; t++) {
        int r = m0 + wm + t * 16 + g;
#pragma unroll
        for (int nt = 0; nt < 8; nt++) {
            int c = wn + nt * 8 + 2 * tg;
            float b0 = 0.f, b1 = 0.f;
            if (BIAS) { b0 = bias[c]; b1 = bias[c + 1]; }
            float v0 = d[t][nt][0] + b0, v1 = d[t][nt][1] + b1;
            float v2 = d[t][nt][2] + b0, v3 = d[t][nt][3] + b1;
            if (GOUT) {
                v0 = gelu_f(v0); v1 = gelu_f(v1);
                v2 = gelu_f(v2); v3 = gelu_f(v3);
            }
            if (TMIX) {
#pragma unroll
                for (int m = 0; m < 4; m++) {
                    float w0 = wbs[m * 128 + c], w1 = wbs[m * 128 + c + 1];
                    tp[t * 2 + 0][m] += v0 * w0 + v1 * w1;
                    tp[t * 2 + 1][m] += v2 * w0 + v3 * w1;
                }
            } else {
                if (r < rows)
                    *(float2*)(C + (long)r * 128 + c) = make_float2(v0, v1);
                if (r + 8 < rows)
                    *(float2*)(C + (long)(r + 8) * 128 + c) = make_float2(v2, v3);
            }
        }
    }

    if (TMIX) {
        // reduce over the 4 lanes of each quad (tg bits = lane bits 0,1)
#pragma unroll
        for (int off = 1; off < 4; off <<= 1)
#pragma unroll
            for (int s = 0; s < 4; s++)
#pragma unroll
                for (int m = 0; m < 4; m++)
                    tp[s][m] += __shfl_xor_sync(0xffffffffu, tp[s][m], off);
        if (tg == 0) {
#pragma unroll
            for (int s = 0; s < 4; s++) {
                int rl = wm + g + ((s & 1) ? 8 : 0) + ((s >> 1) ? 16 : 0);
#pragma unroll
                for (int m = 0; m < 4; m++) atomicAdd(&Tred[rl][m], tp[s][m]);
            }
        }
        __syncthreads();
        if (tid < 128) {
            int r = m0 + tid;
            if (r < rows)
                *(float4*)(g_T + (long)r * 4) =
                    make_float4(Tred[tid][0], Tred[tid][1], Tred[tid][2], Tred[tid][3]);
        }
    }
}

// ---------------- edge counting sort by dst ----------------
__global__ void k_hist(const void* __restrict__ EI) {
    for (int e = blockIdx.x * blockDim.x + threadIdx.x; e < NE;
         e += gridDim.x * blockDim.x) {
        int d = edge_at(EI, 1, e);
        if (d >= 0 && d < NN) atomicAdd(&g_deg[d], 1);
    }
}

__global__ void k_scan() {
    __shared__ int smv[1024];
    int t = threadIdx.x;
    const int CH = 49; // 1024*49 >= 50000
    int base = t * CH;
    int s = 0;
    for (int i = 0; i < CH; i++) {
        int idx = base + i;
        if (idx < NN) s += g_deg[idx];
    }
    smv[t] = s;
    __syncthreads();
    for (int off = 1; off < 1024; off <<= 1) {
        int v = (t >= off) ? smv[t - off] : 0;
        __syncthreads();
        smv[t] += v;
        __syncthreads();
    }
    int run = smv[t] - s;
    for (int i = 0; i < CH; i++) {
        int idx = base + i;
        if (idx < NN) {
            g_off[idx] = run;
            g_cur[idx] = run;
            run += g_deg[idx];
        }
    }
    if (t == 0) g_off[NN] = NE;
}

__global__ void k_scatter(const void* __restrict__ EI) {
    for (int e = blockIdx.x * blockDim.x + threadIdx.x; e < NE;
         e += gridDim.x * blockDim.x) {
        int d = edge_at(EI, 1, e);
        int s = edge_at(EI, 0, e);
        if (d >= 0 && d < NN) {
            int p = atomicAdd(&g_cur[d], 1);
            g_srcs[p] = s;
        }
    }
}

// ---------------- per-node aggregation (warp per node, 2-edge unroll) -----
// acc[h][m] = sum_{e:dst=n} H[src,h]*T[src,m];  S[m] = sum T[src,m]
// aggnode[n][h] = gelu( (sum_m gelu(acc[h][m]) * S[m]) / max(deg,1) )
__global__ void k_agg() {
    int warp = threadIdx.x >> 5, lane = threadIdx.x & 31;
    int n = blockIdx.x * 8 + warp;
    if (n >= NN) return;
    int beg = g_off[n], end = g_off[n + 1];
    float a0[4] = {0, 0, 0, 0}, a1[4] = {0, 0, 0, 0};
    float a2[4] = {0, 0, 0, 0}, a3[4] = {0, 0, 0, 0};
    float S[4] = {0, 0, 0, 0};
    int i = beg;
    for (; i + 1 < end; i += 2) {
        int s0 = g_srcs[i], s1 = g_srcs[i + 1];
        float4 ta = *(const float4*)(g_T + (long)s0 * 4);
        float4 tb = *(const float4*)(g_T + (long)s1 * 4);
        const float* ha = g_H + (long)s0 * 128;
        const float* hb = g_H + (long)s1 * 128;
        float p0 = ha[lane], p1 = ha[lane + 32], p2 = ha[lane + 64], p3 = ha[lane + 96];
        float q0 = hb[lane], q1 = hb[lane + 32], q2 = hb[lane + 64], q3 = hb[lane + 96];
        S[0] += ta.x + tb.x; S[1] += ta.y + tb.y;
        S[2] += ta.z + tb.z; S[3] += ta.w + tb.w;
        a0[0] += p0 * ta.x + q0 * tb.x; a0[1] += p0 * ta.y + q0 * tb.y;
        a0[2] += p0 * ta.z + q0 * tb.z; a0[3] += p0 * ta.w + q0 * tb.w;
        a1[0] += p1 * ta.x + q1 * tb.x; a1[1] += p1 * ta.y + q1 * tb.y;
        a1[2] += p1 * ta.z + q1 * tb.z; a1[3] += p1 * ta.w + q1 * tb.w;
        a2[0] += p2 * ta.x + q2 * tb.x; a2[1] += p2 * ta.y + q2 * tb.y;
        a2[2] += p2 * ta.z + q2 * tb.z; a2[3] += p2 * ta.w + q2 * tb.w;
        a3[0] += p3 * ta.x + q3 * tb.x; a3[1] += p3 * ta.y + q3 * tb.y;
        a3[2] += p3 * ta.z + q3 * tb.z; a3[3] += p3 * ta.w + q3 * tb.w;
    }
    if (i < end) {
        int s0 = g_srcs[i];
        float4 ta = *(const float4*)(g_T + (long)s0 * 4);
        const float* ha = g_H + (long)s0 * 128;
        float p0 = ha[lane], p1 = ha[lane + 32], p2 = ha[lane + 64], p3 = ha[lane + 96];
        S[0] += ta.x; S[1] += ta.y; S[2] += ta.z; S[3] += ta.w;
        a0[0] += p0 * ta.x; a0[1] += p0 * ta.y; a0[2] += p0 * ta.z; a0[3] += p0 * ta.w;
        a1[0] += p1 * ta.x; a1[1] += p1 * ta.y; a1[2] += p1 * ta.z; a1[3] += p1 * ta.w;
        a2[0] += p2 * ta.x; a2[1] += p2 * ta.y; a2[2] += p2 * ta.z; a2[3] += p2 * ta.w;
        a3[0] += p3 * ta.x; a3[1] += p3 * ta.y; a3[2] += p3 * ta.z; a3[3] += p3 * ta.w;
    }
    int cnt = end - beg;
    float inv = 1.0f / (float)(cnt > 1 ? cnt : 1);
    float* outp = g_aggnode + (long)n * 128;
    outp[lane] = gelu_f(
        (gelu_f(a0[0]) * S[0] + gelu_f(a0[1]) * S[1] + gelu_f(a0[2]) * S[2] +
         gelu_f(a0[3]) * S[3]) * inv);
    outp[lane + 32] = gelu_f(
        (gelu_f(a1[0]) * S[0] + gelu_f(a1[1]) * S[1] + gelu_f(a1[2]) * S[2] +
         gelu_f(a1[3]) * S[3]) * inv);
    outp[lane + 64] = gelu_f(
        (gelu_f(a2[0]) * S[0] + gelu_f(a2[1]) * S[1] + gelu_f(a2[2]) * S[2] +
         gelu_f(a2[3]) * S[3]) * inv);
    outp[lane + 96] = gelu_f(
        (gelu_f(a3[0]) * S[0] + gelu_f(a3[1]) * S[1] + gelu_f(a3[2]) * S[2] +
         gelu_f(a3[3]) * S[3]) * inv);
}

// ---------------- host launch: kernel launches ONLY ----------------
extern "C" void kernel_launch(void* const* d_in, const int* in_sizes, int n_in,
                              void* d_out, int out_size) {
    const float* X = (const float*)d_in[0];
    const void* EI = d_in[1];
    const float* W1 = (const float*)d_in[2];
    const float* b1 = (const float*)d_in[3];
    const float* WA = (const float*)d_in[4];
    const float* WB = (const float*)d_in[5];
    const float* W2 = (const float*)d_in[6];
    const float* b2 = (const float*)d_in[7];
    float* out = (float*)d_out;

    k_zerodeg<<<(NN + 255) / 256, 256>>>();
    k_detect<<<256, 256>>>((const unsigned int*)EI);

    int gg = (NN + 127) / 128; // 391
    // H = gelu(X W1^T + b1)
    k_gemm_bf<128, true, true, false, false><<<gg, 256>>>(
        X, -1, -1, b1, W1, nullptr, nullptr, 1, NN);
    // T = gelu(H WA^T) WB^T   (G never materialized)
    k_gemm_bf<128, true, false, false, true><<<gg, 256>>>(
        nullptr, 1, -1, nullptr, WA, WB, nullptr, -1, NN);

    // edge counting sort by dst
    k_hist<<<512, 256>>>(EI);
    k_scan<<<1, 1024>>>();
    k_scatter<<<512, 256>>>(EI);

    // fused aggregation (+ concat-gelu on the agg half)
    k_agg<<<(NN + 7) / 8, 256>>>();

    // out = [gelu(agg) | gelu(H)] W2^T + b2   (virtual concat)
    k_gemm_bf<256, false, true, true, false><<<gg, 256>>>(
        nullptr, 5, 1, b2, W2, nullptr, out, -1, NN);
}

// round 9
// speedup vs baseline: 1.4030x; 1.0123x over previous
#include <cuda_runtime.h>
#include <cuda_bf16.h>
#include <cstdint>

#define NN 50000
#define NE 400000
#define DD 128
#define MM 4

// ---------------- device scratch ----------------
__device__ __align__(16) float g_H[NN * DD];       // 1: H = gelu(X W1^T + b1)
__device__ __align__(16) float g_aggnode[NN * DD]; // 5: gelu(aggregated features)
__device__ __align__(16) float g_T[NN * MM];       // per-node hyper weights
__device__ __align__(16) unsigned g_W1hi[DD * DD / 2];
__device__ __align__(16) unsigned g_W1lo[DD * DD / 2];
__device__ __align__(16) unsigned g_WAhi[DD * DD / 2];
__device__ __align__(16) unsigned g_WAlo[DD * DD / 2];
__device__ __align__(16) unsigned g_W2hi[DD * DD];
__device__ __align__(16) unsigned g_W2lo[DD * DD];
__device__ int g_deg[NN];
__device__ int g_off[NN + 1];
__device__ int g_cur[NN];
__device__ int g_srcs[NE];
__device__ int g_is32; // 1 if edge_index is int32, 0 if int64

__device__ __forceinline__ float* get_buf(int id) {
    switch (id) {
        case 1: return g_H;
        case 5: return g_aggnode;
    }
    return g_H;
}
__device__ __forceinline__ const unsigned* get_whi(int id) {
    switch (id) {
        case 0: return g_W1hi;
        case 1: return g_WAhi;
        case 2: return g_W2hi;
    }
    return g_W1hi;
}
__device__ __forceinline__ const unsigned* get_wlo(int id) {
    switch (id) {
        case 0: return g_W1lo;
        case 1: return g_WAlo;
        case 2: return g_W2lo;
    }
    return g_W1lo;
}

// ---------------- helpers ----------------
__device__ __forceinline__ float gelu_f(float x) {
    return 0.5f * x * (1.0f + erff(x * 0.7071067811865476f));
}

__device__ __forceinline__ unsigned pack2bf(float x, float y) {
    __nv_bfloat162 p = __floats2bfloat162_rn(x, y);
    return *reinterpret_cast<unsigned*>(&p);
}

// split (x,y) into hi bf16 pair + residual-lo bf16 pair
__device__ __forceinline__ void split2(float x, float y, unsigned& hi, unsigned& lo) {
    __nv_bfloat16 hx = __float2bfloat16(x);
    __nv_bfloat16 hy = __float2bfloat16(y);
    __nv_bfloat162 ph;
    ph.x = hx;
    ph.y = hy;
    hi = *reinterpret_cast<unsigned*>(&ph);
    lo = pack2bf(x - __bfloat162float(hx), y - __bfloat162float(hy));
}

__device__ __forceinline__ void mma_bf16(float* d, const unsigned* a,
                                         unsigned b0, unsigned b1) {
    asm volatile(
        "mma.sync.aligned.m16n8k16.row.col.f32.bf16.bf16.f32 "
        "{%0,%1,%2,%3}, {%4,%5,%6,%7}, {%8,%9}, {%0,%1,%2,%3};\n"
        : "+f"(d[0]), "+f"(d[1]), "+f"(d[2]), "+f"(d[3])
        : "r"(a[0]), "r"(a[1]), "r"(a[2]), "r"(a[3]), "r"(b0), "r"(b1));
}

// permuted physical column for logical k-pair p (0..15 within a 32-wide chunk):
// within each 8-pair sub-chunk, pairs tg and tg+4 land adjacent -> LDS.64 frags
__device__ __forceinline__ int physcol(int p) {
    return ((p >> 3) << 3) | (((p & 7) & 3) << 1) | ((p & 7) >> 2);
}

// edge accessor robust to int32 vs int64 storage. which: 0 = src, 1 = dst.
__device__ __forceinline__ int edge_at(const void* EI, int which, int e) {
    if (g_is32) return ((const int*)EI)[which * NE + e];
    return (int)((const long long*)EI)[which * NE + e];
}

// ---------------- init ----------------
__global__ void k_zerodeg() {
    int i = blockIdx.x * blockDim.x + threadIdx.x;
    if (i < NN) g_deg[i] = 0;
    if (i == 0) g_is32 = 0;
}

__global__ void k_detect(const unsigned int* __restrict__ w) {
    unsigned v = 0;
    for (int j = blockIdx.x * blockDim.x + threadIdx.x; j < NE;
         j += gridDim.x * blockDim.x)
        v |= w[2 * j + 1];
    if (v) g_is32 = 1;
}

// ---------------- pre-split weights into bf16 hi/lo pairs ----------------
// pair index space: W1 [0,8192), WA [8192,16384), W2 [16384,32768)
__global__ void k_wsplit(const float* __restrict__ W1, const float* __restrict__ WA,
                         const float* __restrict__ W2) {
    int i = blockIdx.x * blockDim.x + threadIdx.x;
    if (i >= 32768) return;
    const float* src;
    unsigned *dh, *dl;
    int p;
    if (i < 8192) {
        src = W1; dh = g_W1hi; dl = g_W1lo; p = i;
    } else if (i < 16384) {
        src = WA; dh = g_WAhi; dl = g_WAlo; p = i - 8192;
    } else {
        src = W2; dh = g_W2hi; dl = g_W2lo; p = i - 16384;
    }
    float2 v = *(const float2*)(src + 2 * p);
    unsigned h, l;
    split2(v.x, v.y, h, l);
    dh[p] = h;
    dl[p] = l;
}

// ---------------- bf16-split tensor-core GEMM (3-term compensated) --------
// C[m][n] = act( sum_k A[m][k] * W[n][k] + bias[n] ),  N = 128.
// A row-major stride 128 (SPLITA: k<128 from A1, k>=128 from gelu(A2)).
// Weights pre-split in global (wId). CTA 128x128, 8 warps (4M x 2N),
// warp tile 32x64, k-chunk 32, permuted-pair smem, LDS.64 fragments.
// TMIX: skip C write; instead T[m][j] = sum_n gelu(C[m][n]) * WB[j][n].
template <int K, bool GOUT, bool BIAS, bool SPLITA, bool TMIX>
__global__ void __launch_bounds__(256, 2)
k_gemm_bf(const float* __restrict__ Aext, int aId, int a2Id,
          const float* __restrict__ bias, int wId, const float* __restrict__ WB,
          float* __restrict__ Cext, int cId, int rows) {
    __shared__ __align__(16) unsigned As[2][128][20]; // [hi/lo][m][permuted pair]
    __shared__ __align__(16) unsigned Bs[2][128][20];
    __shared__ float Tred[128][4];
    __shared__ float wbs[4 * 128];

    const float* A1 = Aext ? Aext : get_buf(aId);
    const float* A2 = SPLITA ? get_buf(a2Id) : nullptr;
    const unsigned* Whi = get_whi(wId);
    const unsigned* Wlo = get_wlo(wId);
    float* C = Cext ? Cext : get_buf(cId);
    const int K2 = K / 2;

    int tid = threadIdx.x;
    int wid = tid >> 5, lane = tid & 31;
    int wm = (wid >> 1) * 32;  // warp M base
    int wn = (wid & 1) * 64;   // warp N base
    int g = lane >> 2, tg = lane & 3;
    int m0 = blockIdx.x * 128;

    if (TMIX) {
        for (int i = tid; i < 512; i += 256) wbs[i] = WB[i];
        if (tid < 128) {
            Tred[tid][0] = 0.f; Tred[tid][1] = 0.f;
            Tred[tid][2] = 0.f; Tred[tid][3] = 0.f;
        }
    }

    float d[2][8][4];
#pragma unroll
    for (int t = 0; t < 2; t++)
#pragma unroll
        for (int nt = 0; nt < 8; nt++)
#pragma unroll
            for (int j = 0; j < 4; j++) d[t][nt][j] = 0.f;

    for (int kc = 0; kc < K; kc += 32) {
        const float* Ap = A1;
        int kk = kc;
        bool ag = false;
        if (SPLITA && kc >= 128) {
            Ap = A2;
            kk = kc - 128;
            ag = true;
        }
        // cooperative stage: 4 iterations, each thread 1 float4 of A + uint2x2 of B
#pragma unroll
        for (int i = 0; i < 4; ++i) {
            int f = tid + i * 256;   // 0..1023
            int m = f >> 3;          // 0..127
            int kq = (f & 7) << 2;   // 0,4,...,28
            int p = kq >> 1;         // even pair index 0..14
            int c0 = physcol(p);     // pair p
            int c1 = c0 + 2;         // pair p+1 (even-p property)
            // ---- A: load fp32, split ----
            int gm = m0 + m;
            float4 v = make_float4(0.f, 0.f, 0.f, 0.f);
            if (gm < rows) v = *(const float4*)(Ap + (long)gm * 128 + kk + kq);
            if (SPLITA && ag) {
                v.x = gelu_f(v.x); v.y = gelu_f(v.y);
                v.z = gelu_f(v.z); v.w = gelu_f(v.w);
            }
            unsigned h0, l0, h1, l1;
            split2(v.x, v.y, h0, l0);
            split2(v.z, v.w, h1, l1);
            As[0][m][c0] = h0; As[0][m][c1] = h1;
            As[1][m][c0] = l0; As[1][m][c1] = l1;
            // ---- B: pre-split packed pairs straight from global ----
            long wbase = (long)m * K2 + (kc >> 1) + p;
            uint2 bh = *(const uint2*)(Whi + wbase);
            uint2 bl = *(const uint2*)(Wlo + wbase);
            Bs[0][m][c0] = bh.x; Bs[0][m][c1] = bh.y;
            Bs[1][m][c0] = bl.x; Bs[1][m][c1] = bl.y;
        }
        __syncthreads();

#pragma unroll
        for (int ks = 0; ks < 2; ++ks) {
            int base = ks * 8 + 2 * tg;
            unsigned ah[2][4], al[2][4];
#pragma unroll
            for (int t = 0; t < 2; t++) {
                int r0 = wm + t * 16 + g;
                uint2 u0 = *(const uint2*)&As[0][r0][base];
                uint2 u1 = *(const uint2*)&As[0][r0 + 8][base];
                ah[t][0] = u0.x; ah[t][1] = u1.x; ah[t][2] = u0.y; ah[t][3] = u1.y;
                uint2 w0 = *(const uint2*)&As[1][r0][base];
                uint2 w1 = *(const uint2*)&As[1][r0 + 8][base];
                al[t][0] = w0.x; al[t][1] = w1.x; al[t][2] = w0.y; al[t][3] = w1.y;
            }
#pragma unroll
            for (int nt = 0; nt < 8; nt++) {
                int n0 = wn + nt * 8 + g;
                uint2 bh = *(const uint2*)&Bs[0][n0][base];
                uint2 bl = *(const uint2*)&Bs[1][n0][base];
#pragma unroll
                for (int t = 0; t < 2; t++) {
                    mma_bf16(d[t][nt], ah[t], bh.x, bh.y); // hi*hi
                    mma_bf16(d[t][nt], al[t], bh.x, bh.y); // lo*hi
                    mma_bf16(d[t][nt], ah[t], bl.x, bl.y); // hi*lo
                }
            }
        }
        __syncthreads();
    }

    // ---------------- epilogue ----------------
    float tp[4][4];
    if (TMIX) {
#pragma unroll
        for (int s = 0; s < 4; s++)
#pragma unroll
            for (int m = 0; m < 4; m++) tp[s][m] = 0.f;
    }
#pragma unroll
    for (int t = 0; t < 2; t++) {
        int r = m0 + wm + t * 16 + g;
#pragma unroll
        for (int nt = 0; nt < 8; nt++) {
            int c = wn + nt * 8 + 2 * tg;
            float b0 = 0.f, b1 = 0.f;
            if (BIAS) { b0 = bias[c]; b1 = bias[c + 1]; }
            float v0 = d[t][nt][0] + b0, v1 = d[t][nt][1] + b1;
            float v2 = d[t][nt][2] + b0, v3 = d[t][nt][3] + b1;
            if (GOUT) {
                v0 = gelu_f(v0); v1 = gelu_f(v1);
                v2 = gelu_f(v2); v3 = gelu_f(v3);
            }
            if (TMIX) {
#pragma unroll
                for (int m = 0; m < 4; m++) {
                    float w0 = wbs[m * 128 + c], w1 = wbs[m * 128 + c + 1];
                    tp[t * 2 + 0][m] += v0 * w0 + v1 * w1;
                    tp[t * 2 + 1][m] += v2 * w0 + v3 * w1;
                }
            } else {
                if (r < rows)
                    *(float2*)(C + (long)r * 128 + c) = make_float2(v0, v1);
                if (r + 8 < rows)
                    *(float2*)(C + (long)(r + 8) * 128 + c) = make_float2(v2, v3);
            }
        }
    }

    if (TMIX) {
#pragma unroll
        for (int off = 1; off < 4; off <<= 1)
#pragma unroll
            for (int s = 0; s < 4; s++)
#pragma unroll
                for (int m = 0; m < 4; m++)
                    tp[s][m] += __shfl_xor_sync(0xffffffffu, tp[s][m], off);
        if (tg == 0) {
#pragma unroll
            for (int s = 0; s < 4; s++) {
                int rl = wm + g + ((s & 1) ? 8 : 0) + ((s >> 1) ? 16 : 0);
#pragma unroll
                for (int m = 0; m < 4; m++) atomicAdd(&Tred[rl][m], tp[s][m]);
            }
        }
        __syncthreads();
        if (tid < 128) {
            int r = m0 + tid;
            if (r < rows)
                *(float4*)(g_T + (long)r * 4) =
                    make_float4(Tred[tid][0], Tred[tid][1], Tred[tid][2], Tred[tid][3]);
        }
    }
}

// ---------------- edge counting sort by dst ----------------
__global__ void k_hist(const void* __restrict__ EI) {
    for (int e = blockIdx.x * blockDim.x + threadIdx.x; e < NE;
         e += gridDim.x * blockDim.x) {
        int d = edge_at(EI, 1, e);
        if (d >= 0 && d < NN) atomicAdd(&g_deg[d], 1);
    }
}

__global__ void k_scan() {
    __shared__ int smv[1024];
    int t = threadIdx.x;
    const int CH = 49; // 1024*49 >= 50000
    int base = t * CH;
    int s = 0;
    for (int i = 0; i < CH; i++) {
        int idx = base + i;
        if (idx < NN) s += g_deg[idx];
    }
    smv[t] = s;
    __syncthreads();
    for (int off = 1; off < 1024; off <<= 1) {
        int v = (t >= off) ? smv[t - off] : 0;
        __syncthreads();
        smv[t] += v;
        __syncthreads();
    }
    int run = smv[t] - s;
    for (int i = 0; i < CH; i++) {
        int idx = base + i;
        if (idx < NN) {
            g_off[idx] = run;
            g_cur[idx] = run;
            run += g_deg[idx];
        }
    }
    if (t == 0) g_off[NN] = NE;
}

__global__ void k_scatter(const void* __restrict__ EI) {
    for (int e = blockIdx.x * blockDim.x + threadIdx.x; e < NE;
         e += gridDim.x * blockDim.x) {
        int d = edge_at(EI, 1, e);
        int s = edge_at(EI, 0, e);
        if (d >= 0 && d < NN) {
            int p = atomicAdd(&g_cur[d], 1);
            g_srcs[p] = s;
        }
    }
}

// ---------------- per-node aggregation (warp per node, 4-edge unroll) -----
// acc[h][m] = sum_{e:dst=n} H[src,h]*T[src,m];  S[m] = sum T[src,m]
// aggnode[n][h] = gelu( (sum_m gelu(acc[h][m]) * S[m]) / max(deg,1) )
__global__ void k_agg() {
    int warp = threadIdx.x >> 5, lane = threadIdx.x & 31;
    int n = blockIdx.x * 8 + warp;
    if (n >= NN) return;
    int beg = g_off[n], end = g_off[n + 1];
    float acc[4][4]; // [h-seg][mix]
#pragma unroll
    for (int sg = 0; sg < 4; sg++)
#pragma unroll
        for (int m = 0; m < 4; m++) acc[sg][m] = 0.f;
    float S[4] = {0, 0, 0, 0};
    int i = beg;
    for (; i + 3 < end; i += 4) {
        int s[4];
        float4 t4[4];
        float hv[4][4];
#pragma unroll
        for (int e = 0; e < 4; e++) s[e] = g_srcs[i + e];
#pragma unroll
        for (int e = 0; e < 4; e++) {
            t4[e] = *(const float4*)(g_T + (long)s[e] * 4);
            const float* h = g_H + (long)s[e] * 128;
            hv[e][0] = h[lane]; hv[e][1] = h[lane + 32];
            hv[e][2] = h[lane + 64]; hv[e][3] = h[lane + 96];
        }
#pragma unroll
        for (int e = 0; e < 4; e++) {
            float tm[4] = {t4[e].x, t4[e].y, t4[e].z, t4[e].w};
#pragma unroll
            for (int m = 0; m < 4; m++) {
                S[m] += tm[m];
#pragma unroll
                for (int sg = 0; sg < 4; sg++) acc[sg][m] += hv[e][sg] * tm[m];
            }
        }
    }
    for (; i < end; ++i) {
        int s0 = g_srcs[i];
        float4 t4 = *(const float4*)(g_T + (long)s0 * 4);
        const float* h = g_H + (long)s0 * 128;
        float hv[4] = {h[lane], h[lane + 32], h[lane + 64], h[lane + 96]};
        float tm[4] = {t4.x, t4.y, t4.z, t4.w};
#pragma unroll
        for (int m = 0; m < 4; m++) {
            S[m] += tm[m];
#pragma unroll
            for (int sg = 0; sg < 4; sg++) acc[sg][m] += hv[sg] * tm[m];
        }
    }
    int cnt = end - beg;
    float inv = 1.0f / (float)(cnt > 1 ? cnt : 1);
    float* outp = g_aggnode + (long)n * 128;
#pragma unroll
    for (int sg = 0; sg < 4; sg++) {
        outp[lane + sg * 32] = gelu_f(
            (gelu_f(acc[sg][0]) * S[0] + gelu_f(acc[sg][1]) * S[1] +
             gelu_f(acc[sg][2]) * S[2] + gelu_f(acc[sg][3]) * S[3]) * inv);
    }
}

// ---------------- host launch: kernel launches ONLY ----------------
extern "C" void kernel_launch(void* const* d_in, const int* in_sizes, int n_in,
                              void* d_out, int out_size) {
    const float* X = (const float*)d_in[0];
    const void* EI = d_in[1];
    const float* W1 = (const float*)d_in[2];
    const float* b1 = (const float*)d_in[3];
    const float* WA = (const float*)d_in[4];
    const float* WB = (const float*)d_in[5];
    const float* W2 = (const float*)d_in[6];
    const float* b2 = (const float*)d_in[7];
    float* out = (float*)d_out;

    k_zerodeg<<<(NN + 255) / 256, 256>>>();
    k_detect<<<256, 256>>>((const unsigned int*)EI);
    k_wsplit<<<128, 256>>>(W1, WA, W2);

    int gg = (NN + 127) / 128; // 391
    // H = gelu(X W1^T + b1)
    k_gemm_bf<128, true, true, false, false><<<gg, 256>>>(
        X, -1, -1, b1, 0, nullptr, nullptr, 1, NN);
    // T = gelu(H WA^T) WB^T   (G never materialized)
    k_gemm_bf<128, true, false, false, true><<<gg, 256>>>(
        nullptr, 1, -1, nullptr, 1, WB, nullptr, -1, NN);

    // edge counting sort by dst
    k_hist<<<512, 256>>>(EI);
    k_scan<<<1, 1024>>>();
    k_scatter<<<512, 256>>>(EI);

    // fused aggregation (+ concat-gelu on the agg half)
    k_agg<<<(NN + 7) / 8, 256>>>();

    // out = [gelu(agg) | gelu(H)] W2^T + b2   (virtual concat)
    k_gemm_bf<256, false, true, true, false><<<gg, 256>>>(
        nullptr, 5, 1, b2, 2, nullptr, out, -1, NN);
}

// round 11
// speedup vs baseline: 1.4229x; 1.0142x over previous
#include <cuda_runtime.h>
#include <cuda_bf16.h>
#include <cstdint>

#define NN 50000
#define NE 400000
#define DD 128
#define MM 4

// ---------------- device scratch ----------------
__device__ __align__(16) float g_H[NN * DD];       // 1: H = gelu(X W1^T + b1)
__device__ __align__(16) float g_aggnode[NN * DD]; // 5: gelu(aggregated features)
__device__ __align__(16) float g_T[NN * MM];       // per-node hyper weights
__device__ __align__(16) unsigned g_W1hi[DD * DD / 2];
__device__ __align__(16) unsigned g_W1lo[DD * DD / 2];
__device__ __align__(16) unsigned g_WAhi[DD * DD / 2];
__device__ __align__(16) unsigned g_WAlo[DD * DD / 2];
__device__ __align__(16) unsigned g_W2hi[DD * DD];
__device__ __align__(16) unsigned g_W2lo[DD * DD];
__device__ int g_deg[NN];
__device__ int g_off[NN + 1];
__device__ int g_cur[NN];
__device__ int g_srcs[NE];
__device__ int g_is32; // 1 if edge_index is int32, 0 if int64

__device__ __forceinline__ float* get_buf(int id) {
    switch (id) {
        case 1: return g_H;
        case 5: return g_aggnode;
    }
    return g_H;
}
__device__ __forceinline__ const unsigned* get_whi(int id) {
    switch (id) {
        case 0: return g_W1hi;
        case 1: return g_WAhi;
        case 2: return g_W2hi;
    }
    return g_W1hi;
}
__device__ __forceinline__ const unsigned* get_wlo(int id) {
    switch (id) {
        case 0: return g_W1lo;
        case 1: return g_WAlo;
        case 2: return g_W2lo;
    }
    return g_W1lo;
}

// ---------------- helpers ----------------
__device__ __forceinline__ float gelu_f(float x) {
    return 0.5f * x * (1.0f + erff(x * 0.7071067811865476f));
}

__device__ __forceinline__ unsigned pack2bf(float x, float y) {
    __nv_bfloat162 p = __floats2bfloat162_rn(x, y);
    return *reinterpret_cast<unsigned*>(&p);
}

// split (x,y) into hi bf16 pair + residual-lo bf16 pair
__device__ __forceinline__ void split2(float x, float y, unsigned& hi, unsigned& lo) {
    __nv_bfloat16 hx = __float2bfloat16(x);
    __nv_bfloat16 hy = __float2bfloat16(y);
    __nv_bfloat162 ph;
    ph.x = hx;
    ph.y = hy;
    hi = *reinterpret_cast<unsigned*>(&ph);
    lo = pack2bf(x - __bfloat162float(hx), y - __bfloat162float(hy));
}

__device__ __forceinline__ void mma_bf16(float* d, const unsigned* a,
                                         unsigned b0, unsigned b1) {
    asm volatile(
        "mma.sync.aligned.m16n8k16.row.col.f32.bf16.bf16.f32 "
        "{%0,%1,%2,%3}, {%4,%5,%6,%7}, {%8,%9}, {%0,%1,%2,%3};\n"
        : "+f"(d[0]), "+f"(d[1]), "+f"(d[2]), "+f"(d[3])
        : "r"(a[0]), "r"(a[1]), "r"(a[2]), "r"(a[3]), "r"(b0), "r"(b1));
}

// physical column for logical k-pair p within an 8-pair (k16) group:
// pairs tg and tg+4 land physically adjacent -> LDS.64 fragment loads
__device__ __forceinline__ int physcol8(int p) {
    return ((p & 3) << 1) | (p >> 2);
}

__device__ __forceinline__ uint32_t smem_u32(const void* p) {
    uint32_t a;
    asm("{ .reg .u64 t; cvta.to.shared.u64 t, %1; cvt.u32.u64 %0, t; }"
        : "=r"(a) : "l"(p));
    return a;
}

#define CP_ASYNC16(dst, src) \
    asm volatile("cp.async.cg.shared.global [%0], [%1], 16;" \
                 :: "r"(dst), "l"(src) : "memory")
#define CP_COMMIT() asm volatile("cp.async.commit_group;" ::: "memory")
#define CP_WAIT0() asm volatile("cp.async.wait_group 0;" ::: "memory")

// edge accessor robust to int32 vs int64 storage. which: 0 = src, 1 = dst.
__device__ __forceinline__ int edge_at(const void* EI, int which, int e) {
    if (g_is32) return ((const int*)EI)[which * NE + e];
    return (int)((const long long*)EI)[which * NE + e];
}

// ---------------- init ----------------
__global__ void k_zerodeg() {
    int i = blockIdx.x * blockDim.x + threadIdx.x;
    if (i < NN) g_deg[i] = 0;
    if (i == 0) g_is32 = 0;
}

__global__ void k_detect(const unsigned int* __restrict__ w) {
    unsigned v = 0;
    for (int j = blockIdx.x * blockDim.x + threadIdx.x; j < NE;
         j += gridDim.x * blockDim.x)
        v |= w[2 * j + 1];
    if (v) g_is32 = 1;
}

// ---------------- pre-split weights into bf16 hi/lo pairs ----------------
// Stored PRE-PERMUTED per 8-pair group (physcol8) so GEMM B staging is raw
// cp.async. pair space: W1 [0,8192), WA [8192,16384), W2 [16384,32768).
__global__ void k_wsplit(const float* __restrict__ W1, const float* __restrict__ WA,
                         const float* __restrict__ W2) {
    int i = blockIdx.x * blockDim.x + threadIdx.x;
    if (i >= 32768) return;
    const float* src;
    unsigned *dh, *dl;
    int p, K2len;
    if (i < 8192) {
        src = W1; dh = g_W1hi; dl = g_W1lo; p = i; K2len = 64;
    } else if (i < 16384) {
        src = WA; dh = g_WAhi; dl = g_WAlo; p = i - 8192; K2len = 64;
    } else {
        src = W2; dh = g_W2hi; dl = g_W2lo; p = i - 16384; K2len = 128;
    }
    float2 v = *(const float2*)(src + 2 * p);
    unsigned h, l;
    split2(v.x, v.y, h, l);
    int n = p / K2len, col = p % K2len;
    int pc = (col & ~7) | physcol8(col & 7);
    dh[n * K2len + pc] = h;
    dl[n * K2len + pc] = l;
}

// ---------------- bf16-split tensor-core GEMM, double-buffered ------------
// C[m][n] = act( sum_k A[m][k] * W[n][k] + bias[n] ),  N = 128.
// A row-major stride 128 (SPLITA: k<128 from A1, k>=128 from gelu(A2)).
// Weights pre-split + pre-permuted in global. CTA 128x128, 8 warps (4Mx2N),
// warp tile 32x64, k-chunk 16, 2-stage smem pipeline, B via cp.async.
// TMIX: skip C write; instead T[m][j] = sum_n gelu(C[m][n]) * WB[j][n].
template <int K, bool GOUT, bool BIAS, bool SPLITA, bool TMIX>
__global__ void __launch_bounds__(256, 2)
k_gemm_bf(const float* __restrict__ Aext, int aId, int a2Id,
          const float* __restrict__ bias, int wId, const float* __restrict__ WB,
          float* __restrict__ Cext, int cId, int rows) {
    __shared__ __align__(16) unsigned sA[2][2][128][10]; // [stage][hi/lo][m][pc]
    __shared__ __align__(16) unsigned sB[2][2][128][12]; // [stage][hi/lo][n][pc]

    const float* A1 = Aext ? Aext : get_buf(aId);
    const float* A2 = SPLITA ? get_buf(a2Id) : nullptr;
    const unsigned* Whi = get_whi(wId);
    const unsigned* Wlo = get_wlo(wId);
    float* C = Cext ? Cext : get_buf(cId);
    const int K2 = K / 2;
    const int NCH = K / 16;

    int tid = threadIdx.x;
    int wid = tid >> 5, lane = tid & 31;
    int wm = (wid >> 1) * 32;  // warp M base
    int wn = (wid & 1) * 64;   // warp N base
    int g = lane >> 2, tg = lane & 3;
    int m0 = blockIdx.x * 128;

    float d[2][8][4];
#pragma unroll
    for (int t = 0; t < 2; t++)
#pragma unroll
        for (int nt = 0; nt < 8; nt++)
#pragma unroll
            for (int j = 0; j < 4; j++) d[t][nt][j] = 0.f;

    // staging helpers
    int brow = tid >> 1, bq = tid & 1; // B: each thread 1 hi + 1 lo cp.async
    auto stageB = [&](int s, int c) {
        uint32_t d0 = smem_u32(&sB[s][0][brow][bq * 4]);
        CP_ASYNC16(d0, Whi + (long)brow * K2 + 8 * c + 4 * bq);
        uint32_t d1 = smem_u32(&sB[s][1][brow][bq * 4]);
        CP_ASYNC16(d1, Wlo + (long)brow * K2 + 8 * c + 4 * bq);
    };
    auto ldgA = [&](int c, float4* vr) {
        const float* Ap = A1;
        int kk = c * 16;
        if (SPLITA && kk >= 128) { Ap = A2; kk -= 128; }
#pragma unroll
        for (int i = 0; i < 2; ++i) {
            int f = tid + (i << 8);
            int m = f >> 2, kq = (f & 3) << 2;
            int gm = m0 + m;
            vr[i] = (gm < rows) ? *(const float4*)(Ap + (long)gm * 128 + kk + kq)
                                : make_float4(0.f, 0.f, 0.f, 0.f);
        }
    };
    auto stsA = [&](int s, int c, float4* vr) {
        bool ag = SPLITA && (c * 16 >= 128);
#pragma unroll
        for (int i = 0; i < 2; ++i) {
            int f = tid + (i << 8);
            int m = f >> 2, kq = (f & 3) << 2;
            int p = kq >> 1; // even
            int c0 = physcol8(p);
            float4 v = vr[i];
            if (ag) {
                v.x = gelu_f(v.x); v.y = gelu_f(v.y);
                v.z = gelu_f(v.z); v.w = gelu_f(v.w);
            }
            unsigned h0, l0, h1, l1;
            split2(v.x, v.y, h0, l0);
            split2(v.z, v.w, h1, l1);
            sA[s][0][m][c0] = h0; sA[s][0][m][c0 + 2] = h1;
            sA[s][1][m][c0] = l0; sA[s][1][m][c0 + 2] = l1;
        }
    };
    auto domma = [&](int s) {
        unsigned ah[2][4], al[2][4];
#pragma unroll
        for (int t = 0; t < 2; t++) {
            int r0 = wm + t * 16 + g;
            uint2 u0 = *(const uint2*)&sA[s][0][r0][2 * tg];
            uint2 u1 = *(const uint2*)&sA[s][0][r0 + 8][2 * tg];
            ah[t][0] = u0.x; ah[t][1] = u1.x; ah[t][2] = u0.y; ah[t][3] = u1.y;
            uint2 w0 = *(const uint2*)&sA[s][1][r0][2 * tg];
            uint2 w1 = *(const uint2*)&sA[s][1][r0 + 8][2 * tg];
            al[t][0] = w0.x; al[t][1] = w1.x; al[t][2] = w0.y; al[t][3] = w1.y;
        }
#pragma unroll
        for (int nt = 0; nt < 8; nt++) {
            int n0 = wn + nt * 8 + g;
            uint2 bh = *(const uint2*)&sB[s][0][n0][2 * tg];
            uint2 bl = *(const uint2*)&sB[s][1][n0][2 * tg];
#pragma unroll
            for (int t = 0; t < 2; t++) {
                mma_bf16(d[t][nt], ah[t], bh.x, bh.y); // hi*hi
                mma_bf16(d[t][nt], al[t], bh.x, bh.y); // lo*hi
                mma_bf16(d[t][nt], ah[t], bl.x, bl.y); // hi*lo
            }
        }
    };

    // ---- prologue: fill stage 0 ----
    {
        stageB(0, 0);
        CP_COMMIT();
        float4 v0[2];
        ldgA(0, v0);
        stsA(0, 0, v0);
        CP_WAIT0();
    }
    __syncthreads();

    // ---- pipelined mainloop ----
    float4 vr[2];
    for (int c = 0; c < NCH; ++c) {
        int cs = c & 1, ns = cs ^ 1;
        bool more = (c + 1 < NCH);
        if (more) {
            stageB(ns, c + 1);
            CP_COMMIT();
            ldgA(c + 1, vr);
        }
        domma(cs);
        if (more) {
            stsA(ns, c + 1, vr);
            CP_WAIT0();
        }
        __syncthreads();
    }

    // ---------------- epilogue ----------------
    float* wbs = (float*)sA;                    // 512 floats, aliased
    float* Tred = (float*)&sA[0][1][0][0];      // 512 floats, aliased (offset 5120B)
    if (TMIX) {
        for (int i = tid; i < 512; i += 256) wbs[i] = WB[i];
        if (tid < 128) {
            Tred[tid * 4 + 0] = 0.f; Tred[tid * 4 + 1] = 0.f;
            Tred[tid * 4 + 2] = 0.f; Tred[tid * 4 + 3] = 0.f;
        }
        __syncthreads();
    }

    float tp[4][4];
    if (TMIX) {
#pragma unroll
        for (int s = 0; s < 4; s++)
#pragma unroll
            for (int m = 0; m < 4; m++) tp[s][m] = 0.f;
    }
#pragma unroll
    for (int t = 0; t < 2; t++) {
        int r = m0 + wm + t * 16 + g;
#pragma unroll
        for (int nt = 0; nt < 8; nt++) {
            int c = wn + nt * 8 + 2 * tg;
            float b0 = 0.f, b1 = 0.f;
            if (BIAS) { b0 = bias[c]; b1 = bias[c + 1]; }
            float v0 = d[t][nt][0] + b0, v1 = d[t][nt][1] + b1;
            float v2 = d[t][nt][2] + b0, v3 = d[t][nt][3] + b1;
            if (GOUT) {
                v0 = gelu_f(v0); v1 = gelu_f(v1);
                v2 = gelu_f(v2); v3 = gelu_f(v3);
            }
            if (TMIX) {
#pragma unroll
                for (int m = 0; m < 4; m++) {
                    float w0 = wbs[m * 128 + c], w1 = wbs[m * 128 + c + 1];
                    tp[t * 2 + 0][m] += v0 * w0 + v1 * w1;
                    tp[t * 2 + 1][m] += v2 * w0 + v3 * w1;
                }
            } else {
                if (r < rows)
                    *(float2*)(C + (long)r * 128 + c) = make_float2(v0, v1);
                if (r + 8 < rows)
                    *(float2*)(C + (long)(r + 8) * 128 + c) = make_float2(v2, v3);
            }
        }
    }

    if (TMIX) {
#pragma unroll
        for (int off = 1; off < 4; off <<= 1)
#pragma unroll
            for (int s = 0; s < 4; s++)
#pragma unroll
                for (int m = 0; m < 4; m++)
                    tp[s][m] += __shfl_xor_sync(0xffffffffu, tp[s][m], off);
        if (tg == 0) {
#pragma unroll
            for (int s = 0; s < 4; s++) {
                int rl = wm + g + ((s & 1) ? 8 : 0) + ((s >> 1) ? 16 : 0);
#pragma unroll
                for (int m = 0; m < 4; m++) atomicAdd(&Tred[rl * 4 + m], tp[s][m]);
            }
        }
        __syncthreads();
        if (tid < 128) {
            int r = m0 + tid;
            if (r < rows)
                *(float4*)(g_T + (long)r * 4) =
                    make_float4(Tred[tid * 4 + 0], Tred[tid * 4 + 1],
                                Tred[tid * 4 + 2], Tred[tid * 4 + 3]);
        }
    }
}

// ---------------- edge counting sort by dst ----------------
__global__ void k_hist(const void* __restrict__ EI) {
    for (int e = blockIdx.x * blockDim.x + threadIdx.x; e < NE;
         e += gridDim.x * blockDim.x) {
        int d = edge_at(EI, 1, e);
        if (d >= 0 && d < NN) atomicAdd(&g_deg[d], 1);
    }
}

__global__ void k_scan() {
    __shared__ int smv[1024];
    int t = threadIdx.x;
    const int CH = 49; // 1024*49 >= 50000
    int base = t * CH;
    int s = 0;
    for (int i = 0; i < CH; i++) {
        int idx = base + i;
        if (idx < NN) s += g_deg[idx];
    }
    smv[t] = s;
    __syncthreads();
    for (int off = 1; off < 1024; off <<= 1) {
        int v = (t >= off) ? smv[t - off] : 0;
        __syncthreads();
        smv[t] += v;
        __syncthreads();
    }
    int run = smv[t] - s;
    for (int i = 0; i < CH; i++) {
        int idx = base + i;
        if (idx < NN) {
            g_off[idx] = run;
            g_cur[idx] = run;
            run += g_deg[idx];
        }
    }
    if (t == 0) g_off[NN] = NE;
}

__global__ void k_scatter(const void* __restrict__ EI) {
    for (int e = blockIdx.x * blockDim.x + threadIdx.x; e < NE;
         e += gridDim.x * blockDim.x) {
        int d = edge_at(EI, 1, e);
        int s = edge_at(EI, 0, e);
        if (d >= 0 && d < NN) {
            int p = atomicAdd(&g_cur[d], 1);
            g_srcs[p] = s;
        }
    }
}

// ---------------- per-node aggregation (warp per node, 4-edge unroll) -----
__global__ void k_agg() {
    int warp = threadIdx.x >> 5, lane = threadIdx.x & 31;
    int n = blockIdx.x * 8 + warp;
    if (n >= NN) return;
    int beg = g_off[n], end = g_off[n + 1];
    float acc[4][4];
#pragma unroll
    for (int sg = 0; sg < 4; sg++)
#pragma unroll
        for (int m = 0; m < 4; m++) acc[sg][m] = 0.f;
    float S[4] = {0, 0, 0, 0};
    int i = beg;
    for (; i + 3 < end; i += 4) {
        int s[4];
        float4 t4[4];
        float hv[4][4];
#pragma unroll
        for (int e = 0; e < 4; e++) s[e] = g_srcs[i + e];
#pragma unroll
        for (int e = 0; e < 4; e++) {
            t4[e] = *(const float4*)(g_T + (long)s[e] * 4);
            const float* h = g_H + (long)s[e] * 128;
            hv[e][0] = h[lane]; hv[e][1] = h[lane + 32];
            hv[e][2] = h[lane + 64]; hv[e][3] = h[lane + 96];
        }
#pragma unroll
        for (int e = 0; e < 4; e++) {
            float tm[4] = {t4[e].x, t4[e].y, t4[e].z, t4[e].w};
#pragma unroll
            for (int m = 0; m < 4; m++) {
                S[m] += tm[m];
#pragma unroll
                for (int sg = 0; sg < 4; sg++) acc[sg][m] += hv[e][sg] * tm[m];
            }
        }
    }
    for (; i < end; ++i) {
        int s0 = g_srcs[i];
        float4 t4 = *(const float4*)(g_T + (long)s0 * 4);
        const float* h = g_H + (long)s0 * 128;
        float hv[4] = {h[lane], h[lane + 32], h[lane + 64], h[lane + 96]};
        float tm[4] = {t4.x, t4.y, t4.z, t4.w};
#pragma unroll
        for (int m = 0; m < 4; m++) {
            S[m] += tm[m];
#pragma unroll
            for (int sg = 0; sg < 4; sg++) acc[sg][m] += hv[sg] * tm[m];
        }
    }
    int cnt = end - beg;
    float inv = 1.0f / (float)(cnt > 1 ? cnt : 1);
    float* outp = g_aggnode + (long)n * 128;
#pragma unroll
    for (int sg = 0; sg < 4; sg++) {
        outp[lane + sg * 32] = gelu_f(
            (gelu_f(acc[sg][0]) * S[0] + gelu_f(acc[sg][1]) * S[1] +
             gelu_f(acc[sg][2]) * S[2] + gelu_f(acc[sg][3]) * S[3]) * inv);
    }
}

// ---------------- host launch: kernel launches ONLY ----------------
extern "C" void kernel_launch(void* const* d_in, const int* in_sizes, int n_in,
                              void* d_out, int out_size) {
    const float* X = (const float*)d_in[0];
    const void* EI = d_in[1];
    const float* W1 = (const float*)d_in[2];
    const float* b1 = (const float*)d_in[3];
    const float* WA = (const float*)d_in[4];
    const float* WB = (const float*)d_in[5];
    const float* W2 = (const float*)d_in[6];
    const float* b2 = (const float*)d_in[7];
    float* out = (float*)d_out;

    k_zerodeg<<<(NN + 255) / 256, 256>>>();
    k_detect<<<256, 256>>>((const unsigned int*)EI);
    k_wsplit<<<128, 256>>>(W1, WA, W2);

    int gg = (NN + 127) / 128; // 391
    // H = gelu(X W1^T + b1)
    k_gemm_bf<128, true, true, false, false><<<gg, 256>>>(
        X, -1, -1, b1, 0, nullptr, nullptr, 1, NN);
    // T = gelu(H WA^T) WB^T   (G never materialized)
    k_gemm_bf<128, true, false, false, true><<<gg, 256>>>(
        nullptr, 1, -1, nullptr, 1, WB, nullptr, -1, NN);

    // edge counting sort by dst
    k_hist<<<512, 256>>>(EI);
    k_scan<<<1, 1024>>>();
    k_scatter<<<512, 256>>>(EI);

    // fused aggregation (+ concat-gelu on the agg half)
    k_agg<<<(NN + 7) / 8, 256>>>();

    // out = [gelu(agg) | gelu(H)] W2^T + b2   (virtual concat)
    k_gemm_bf<256, false, true, true, false><<<gg, 256>>>(
        nullptr, 5, 1, b2, 2, nullptr, out, -1, NN);
}